// round 14
// baseline (speedup 1.0000x reference)
#include <cuda_runtime.h>
#include <cuda_fp16.h>
#include <cstdint>
#include <cstddef>

#define KDIM 256
#define NQ_  1024
#define B_   4
#define NF_  65536

// scratch (__device__ globals: the sanctioned no-alloc path)
__device__ __half g_wh[4 * KDIM * KDIM];   // fp16 weights, [layer][out][in]
__device__ __half g_qh[NQ_ * KDIM];        // fp16 MLP output (logits B operand)

__device__ __forceinline__ uint32_t cvta_s(const void* p) {
    return (uint32_t)__cvta_generic_to_shared(p);
}

#define LDM4(r0, r1, r2, r3, addr) \
    asm volatile("ldmatrix.sync.aligned.m8n8.x4.shared.b16 {%0,%1,%2,%3}, [%4];" \
                 : "=r"(r0), "=r"(r1), "=r"(r2), "=r"(r3) : "r"(addr))

#define MMA16(c, a, b0, b1) \
    asm volatile("mma.sync.aligned.m16n8k16.row.col.f32.f16.f16.f32 " \
                 "{%0,%1,%2,%3},{%4,%5,%6,%7},{%8,%9},{%0,%1,%2,%3};" \
                 : "+f"((c)[0]), "+f"((c)[1]), "+f"((c)[2]), "+f"((c)[3]) \
                 : "r"((a)[0]), "r"((a)[1]), "r"((a)[2]), "r"((a)[3]), "r"(b0), "r"(b1))

#define CP16(dst, src) \
    asm volatile("cp.async.cg.shared.global [%0], [%1], 16;" :: "r"(dst), "l"(src))

#define STS128(addr, v0, v1, v2, v3) \
    asm volatile("st.shared.v4.b32 [%0], {%1,%2,%3,%4};" \
                 :: "r"(addr), "r"(v0), "r"(v1), "r"(v2), "r"(v3))

// ---------------------------------------------------------------------------
// prep: convert the 4 weight matrices f32 -> fp16 (once per launch)
// ---------------------------------------------------------------------------
__global__ void prep_w(const float* __restrict__ W1, const float* __restrict__ W2,
                       const float* __restrict__ W3, const float* __restrict__ W4)
{
    int idx = blockIdx.x * 256 + threadIdx.x;          // 65536 float4 total
    const float* src = (idx < 16384) ? W1 : (idx < 32768) ? W2 : (idx < 49152) ? W3 : W4;
    int off = idx & 16383;
    float4 v = ((const float4*)src)[off];
    __half2 h0 = __floats2half2_rn(v.x, v.y);
    __half2 h1 = __floats2half2_rn(v.z, v.w);
    uint2 u;
    u.x = *(uint32_t*)&h0;
    u.y = *(uint32_t*)&h1;
    ((uint2*)g_wh)[idx] = u;
}

// ---------------------------------------------------------------------------
// Fused 4-layer MLP (unchanged from the 190.6us config; ~15us)
// ---------------------------------------------------------------------------
#define MLP_SMEM (65536 + 49152 + 4096)

__global__ __launch_bounds__(256) void mlp_fused(
    const float* __restrict__ Q, const __half* __restrict__ wh,
    const float* __restrict__ b1, const float* __restrict__ b2,
    const float* __restrict__ b3, const float* __restrict__ b4,
    __half* __restrict__ qh)
{
    extern __shared__ char sm[];
    char*  xb = sm;                        // 2 x 32768
    char*  ws = sm + 65536;                // 3 x 16384
    float* sb = (float*)(sm + 65536 + 49152);

    const int tid = threadIdx.x;
    const int w = tid >> 5, l = tid & 31;
    const int g = l >> 2, t = l & 3;
    const int wm = (w & 1) * 32;
    const int wn = (w >> 1) * 64;
    const int m0 = blockIdx.x * 64;

    sb[tid] = b1[tid]; sb[256 + tid] = b2[tid];
    sb[512 + tid] = b3[tid]; sb[768 + tid] = b4[tid];

#pragma unroll
    for (int i = 0; i < 16; i++) {
        int idx = tid + i * 256;
        int r = idx >> 6, k = (idx & 63) * 4;
        float4 v = *(const float4*)&Q[(size_t)(m0 + r) * KDIM + k];
        __half2 h0 = __floats2half2_rn(v.x, v.y);
        __half2 h1 = __floats2half2_rn(v.z, v.w);
        int chunk = k >> 5, c16 = (k & 31) >> 3, hi = (k >> 2) & 1;
        uint32_t ad = cvta_s(xb + chunk * 4096 + (r & 31) * 128
                             + ((((r >> 5) * 4) + c16) ^ (r & 7)) * 16 + hi * 8);
        asm volatile("st.shared.v2.b32 [%0], {%1,%2};"
                     :: "r"(ad), "r"(*(uint32_t*)&h0), "r"(*(uint32_t*)&h1));
    }

    uint32_t b_addr[4];
    {
        int n = wn + (l & 7) + ((l >> 4) & 1) * 8;
        int ck = (l >> 3) & 1;
#pragma unroll
        for (int p = 0; p < 4; p++) {
            int nn = n + p * 16;
            int cp = (((nn >> 7) * 4 + ck) ^ (nn & 7));
            b_addr[p] = cvta_s(ws + (nn & 127) * 128 + cp * 16);
        }
    }
    uint32_t wst[4];
#pragma unroll
    for (int c = 0; c < 4; c++) {
        int n = tid;
        wst[c] = cvta_s(ws + (n & 127) * 128 + ((((n >> 7) * 4) + c) ^ (n & 7)) * 16);
    }

    __syncthreads();

    for (int L = 0; L < 4; L++) {
        const __half* Wl = wh + (size_t)L * 65536;
        const uint32_t xbase = (uint32_t)(L & 1) * 32768;

        uint32_t a_addr[2];
        {
            int r = wm + (l & 7) + ((l >> 3) & 1) * 8;
            int ck = (l >> 4) & 1;
#pragma unroll
            for (int mt = 0; mt < 2; mt++) {
                int rr = r + mt * 16;
                int cp = (((rr >> 5) * 4 + ck) ^ (rr & 7));
                a_addr[mt] = cvta_s(xb + xbase + (rr & 31) * 128 + cp * 16);
            }
        }

#pragma unroll
        for (int s = 0; s < 2; s++) {
#pragma unroll
            for (int c = 0; c < 4; c++)
                CP16(wst[c] + s * 16384, Wl + (size_t)tid * KDIM + s * 32 + c * 8);
            asm volatile("cp.async.commit_group;");
        }

        float acc[2][8][4];
#pragma unroll
        for (int mt = 0; mt < 2; mt++)
#pragma unroll
            for (int nt = 0; nt < 8; nt++)
#pragma unroll
                for (int i = 0; i < 4; i++) acc[mt][nt][i] = 0.f;

#pragma unroll
        for (int kt = 0; kt < 8; kt++) {
            asm volatile("cp.async.wait_group 1;");
            __syncthreads();
            if (kt < 6) {
                int s = (kt + 2) % 3;
#pragma unroll
                for (int c = 0; c < 4; c++)
                    CP16(wst[c] + s * 16384, Wl + (size_t)tid * KDIM + (kt + 2) * 32 + c * 8);
            }
            asm volatile("cp.async.commit_group;");

            const uint32_t abuf = kt * 4096;
            const uint32_t bbuf = (kt % 3) * 16384;
#pragma unroll
            for (int g16 = 0; g16 < 2; g16++) {
                const uint32_t xo = g16 * 32;
                uint32_t a0[4], a1[4];
                LDM4(a0[0], a0[1], a0[2], a0[3], (a_addr[0] + abuf) ^ xo);
                LDM4(a1[0], a1[1], a1[2], a1[3], (a_addr[1] + abuf) ^ xo);
                uint32_t bf[4][4];
#pragma unroll
                for (int p = 0; p < 4; p++)
                    LDM4(bf[p][0], bf[p][1], bf[p][2], bf[p][3], (b_addr[p] + bbuf) ^ xo);
#pragma unroll
                for (int nt = 0; nt < 8; nt++) {
                    uint32_t q0 = bf[nt >> 1][(nt & 1) * 2];
                    uint32_t q1 = bf[nt >> 1][(nt & 1) * 2 + 1];
                    MMA16(acc[0][nt], a0, q0, q1);
                    MMA16(acc[1][nt], a1, q0, q1);
                }
            }
        }

        __syncthreads();

        if (L < 3) {
            const uint32_t pong = (uint32_t)((L & 1) ^ 1) * 32768;
#pragma unroll
            for (int mt = 0; mt < 2; mt++) {
#pragma unroll
                for (int nt = 0; nt < 8; nt++) {
                    int r = wm + mt * 16 + g;
                    int c = wn + nt * 8 + 2 * t;
                    float bi0 = sb[L * 256 + c], bi1 = sb[L * 256 + c + 1];
                    float v0 = fmaxf(acc[mt][nt][0] + bi0, 0.f);
                    float v1 = fmaxf(acc[mt][nt][1] + bi1, 0.f);
                    float v2 = fmaxf(acc[mt][nt][2] + bi0, 0.f);
                    float v3 = fmaxf(acc[mt][nt][3] + bi1, 0.f);
                    __half2 h01 = __floats2half2_rn(v0, v1);
                    __half2 h23 = __floats2half2_rn(v2, v3);
                    int chunk = c >> 5, c16 = (c & 31) >> 3, bo = (c & 7) * 2;
                    int r8 = r + 8;
                    uint32_t ad0 = cvta_s(xb + pong + chunk * 4096 + (r & 31) * 128
                                   + ((((r >> 5) * 4) + c16) ^ (r & 7)) * 16 + bo);
                    uint32_t ad1 = cvta_s(xb + pong + chunk * 4096 + (r8 & 31) * 128
                                   + ((((r8 >> 5) * 4) + c16) ^ (r8 & 7)) * 16 + bo);
                    asm volatile("st.shared.b32 [%0], %1;" :: "r"(ad0), "r"(*(uint32_t*)&h01));
                    asm volatile("st.shared.b32 [%0], %1;" :: "r"(ad1), "r"(*(uint32_t*)&h23));
                }
            }
        } else {
#pragma unroll
            for (int mt = 0; mt < 2; mt++) {
#pragma unroll
                for (int nt = 0; nt < 8; nt++) {
                    int r = m0 + wm + mt * 16 + g;
                    int c = wn + nt * 8 + 2 * t;
                    float bi0 = sb[768 + c], bi1 = sb[768 + c + 1];
                    __half2 h01 = __floats2half2_rn(acc[mt][nt][0] + bi0, acc[mt][nt][1] + bi1);
                    __half2 h23 = __floats2half2_rn(acc[mt][nt][2] + bi0, acc[mt][nt][3] + bi1);
                    *(__half2*)&qh[(size_t)r * KDIM + c]       = h01;
                    *(__half2*)&qh[(size_t)(r + 8) * KDIM + c] = h23;
                }
            }
        }
        __syncthreads();
    }
}

// ---------------------------------------------------------------------------
// Logits GEMM v8: BARRIER-FREE mainloop.
//  - B: static 64KB tile, loaded once (cp.async), waited fully in prologue;
//    the single __syncthreads after it is the ONLY CTA barrier.
//  - A: per-warp private. Each warp LDGs its own 32 rows (f32), cvt->fp16,
//    STS into its own 2x2KB double buffer; STS->ldmatrix ordered by
//    __syncwarp only. Warps fully independent in the mainloop.
//  Per-warp A layout (rows r=0..31 local, fp16 chunks c=0..3 of 16B):
//    phys = (r&15)*128 + ((((r>>4)*4 + c) ^ (r&7)) * 16
//  ldmatrix deltas: mt1 = base^64, g16=1 = base^32, buffer = +(kt&1)*2048.
// ---------------------------------------------------------------------------
#define LOG_SMEM (8 * 4096 + 8 * 8192)   // A 32KB (8 warps x 2 bufs x 2KB) + B 64KB
#define BOFF 32768

__global__ __launch_bounds__(256, 2)
void gemm_logits(const float* __restrict__ A, const __half* __restrict__ Bh,
                 float* __restrict__ C)
{
    extern __shared__ char sm[];

    const int tid = threadIdx.x;
    const int w = tid >> 5, l = tid & 31;
    const int g = l >> 2, t = l & 3;
    const int wm = (w & 3) * 32;
    const int wn = (w >> 2) * 64;
    const uint32_t wbase = (uint32_t)w * 4096;

    const int nb = blockIdx.x;   // n-inner: nb pair shares the A tile via L2
    const int mb = blockIdx.y;
    const long long bb = blockIdx.z;

    const float* Ab = A + bb * ((long long)NF_ * KDIM) + (size_t)mb * 128 * KDIM;
    const __half* Bb = Bh + bb * ((long long)256 * KDIM) + (size_t)nb * 128 * KDIM;
    float* Cb = C + bb * ((long long)NF_ * 256) + (size_t)mb * 128 * 256 + (size_t)nb * 128;

    // ---- B: whole 64KB tile via cp.async, ONE commit group ----
    {
        int n = tid >> 1, c0 = (tid & 1) * 2;
        uint32_t d0 = cvta_s(sm + BOFF + (n & 63) * 128 + ((((n >> 6) * 4) + c0) ^ (n & 7)) * 16);
        uint32_t d1 = cvta_s(sm + BOFF + (n & 63) * 128 + ((((n >> 6) * 4) + c0 + 1) ^ (n & 7)) * 16);
        const __half* src = Bb + (size_t)n * KDIM + c0 * 8;
#pragma unroll
        for (int s = 0; s < 8; s++) {
            CP16(d0 + s * 8192, src + s * 32);
            CP16(d1 + s * 8192, src + s * 32 + 8);
        }
        asm volatile("cp.async.commit_group;");
    }

    // ---- address setup ----
    // ldmatrix A base (mt=0, g16=0, buf0)
    uint32_t a_lm;
    {
        int r = (l & 7) + ((l >> 3) & 1) * 8;      // 0..15
        int c = (l >> 4) & 1;
        a_lm = cvta_s(sm + wbase + r * 128 + ((c ^ (r & 7)) * 16));
    }
    // ldmatrix B addrs (chunk-relative at BOFF)
    uint32_t b_addr[4];
    {
        int n = wn + (l & 7) + ((l >> 4) & 1) * 8;
        int ck = (l >> 3) & 1;
#pragma unroll
        for (int p = 0; p < 4; p++) {
            int nn = n + p * 16;
            int cp = (((nn >> 6) * 4 + ck) ^ (nn & 7));
            b_addr[p] = cvta_s(sm + BOFF + (nn & 63) * 128 + cp * 16);
        }
    }
    // A STS addrs: lane l -> local row l, fp16 chunk c
    uint32_t a_st[4];
#pragma unroll
    for (int c = 0; c < 4; c++)
        a_st[c] = cvta_s(sm + wbase + (l & 15) * 128
                         + ((((l >> 4) * 4 + c) ^ (l & 7)) * 16));
    // A LDG base: absolute row wm + l
    const float* abase = Ab + (size_t)(wm + l) * KDIM;

    // ---- A(0) prologue: load f32, cvt, STS buf0 ----
#pragma unroll
    for (int h = 0; h < 2; h++) {
        float4 raw[4];
#pragma unroll
        for (int j = 0; j < 4; j++) raw[j] = *(const float4*)(abase + (4 * h + j) * 4);
        uint32_t v[8];
#pragma unroll
        for (int j = 0; j < 4; j++) {
            __half2 lo = __floats2half2_rn(raw[j].x, raw[j].y);
            __half2 hi = __floats2half2_rn(raw[j].z, raw[j].w);
            v[2 * j]     = *(uint32_t*)&lo;
            v[2 * j + 1] = *(uint32_t*)&hi;
        }
        STS128(a_st[2 * h],     v[0], v[1], v[2], v[3]);
        STS128(a_st[2 * h + 1], v[4], v[5], v[6], v[7]);
    }

    float acc[2][8][4];
#pragma unroll
    for (int mt = 0; mt < 2; mt++)
#pragma unroll
        for (int nt = 0; nt < 8; nt++)
#pragma unroll
            for (int i = 0; i < 4; i++) acc[mt][nt][i] = 0.f;

    asm volatile("cp.async.wait_group 0;");   // whole B resident
    __syncthreads();                          // the ONLY CTA barrier

    // A(0) fragments
    uint32_t af0[2][4], af1[2][4];
    LDM4(af0[0][0], af0[0][1], af0[0][2], af0[0][3], a_lm);
    LDM4(af0[1][0], af0[1][1], af0[1][2], af0[1][3], a_lm ^ 64);
    LDM4(af1[0][0], af1[0][1], af1[0][2], af1[0][3], a_lm ^ 32);
    LDM4(af1[1][0], af1[1][1], af1[1][2], af1[1][3], a_lm ^ 32 ^ 64);

    // ---- barrier-free mainloop ----
#pragma unroll
    for (int kt = 0; kt < 8; kt++) {
        const uint32_t abuf = (uint32_t)(kt & 1) * 2048;
        const uint32_t nab  = (uint32_t)((kt + 1) & 1) * 2048;
        const uint32_t bbuf = (uint32_t)kt * 8192;

        // B g0 first half
        uint32_t bf0h[2][4];
        LDM4(bf0h[0][0], bf0h[0][1], bf0h[0][2], bf0h[0][3], b_addr[0] + bbuf);
        LDM4(bf0h[1][0], bf0h[1][1], bf0h[1][2], bf0h[1][3], b_addr[1] + bbuf);

        // LDG A(kt+1) half 0
        float4 raw[4];
        if (kt < 7) {
#pragma unroll
            for (int j = 0; j < 4; j++)
                raw[j] = *(const float4*)(abase + (kt + 1) * 32 + j * 4);
        }

        // MMA g0 nt0-3
#pragma unroll
        for (int nt = 0; nt < 4; nt++) {
            uint32_t q0 = bf0h[nt >> 1][(nt & 1) * 2];
            uint32_t q1 = bf0h[nt >> 1][(nt & 1) * 2 + 1];
            MMA16(acc[0][nt], af0[0], q0, q1);
            MMA16(acc[1][nt], af0[1], q0, q1);
        }

        // B g0 second half
        uint32_t bf0l[2][4];
        LDM4(bf0l[0][0], bf0l[0][1], bf0l[0][2], bf0l[0][3], b_addr[2] + bbuf);
        LDM4(bf0l[1][0], bf0l[1][1], bf0l[1][2], bf0l[1][3], b_addr[3] + bbuf);

        // cvt + STS half 0 into next A buffer
        if (kt < 7) {
            uint32_t v[8];
#pragma unroll
            for (int j = 0; j < 4; j++) {
                __half2 lo = __floats2half2_rn(raw[j].x, raw[j].y);
                __half2 hi = __floats2half2_rn(raw[j].z, raw[j].w);
                v[2 * j]     = *(uint32_t*)&lo;
                v[2 * j + 1] = *(uint32_t*)&hi;
            }
            STS128(a_st[0] + nab, v[0], v[1], v[2], v[3]);
            STS128(a_st[1] + nab, v[4], v[5], v[6], v[7]);
        }

        // MMA g0 nt4-7
#pragma unroll
        for (int nt = 4; nt < 8; nt++) {
            uint32_t q0 = bf0l[(nt - 4) >> 1][(nt & 1) * 2];
            uint32_t q1 = bf0l[(nt - 4) >> 1][(nt & 1) * 2 + 1];
            MMA16(acc[0][nt], af0[0], q0, q1);
            MMA16(acc[1][nt], af0[1], q0, q1);
        }

        // B g1 first half
        uint32_t bf1h[2][4];
        LDM4(bf1h[0][0], bf1h[0][1], bf1h[0][2], bf1h[0][3], (b_addr[0] + bbuf) ^ 32);
        LDM4(bf1h[1][0], bf1h[1][1], bf1h[1][2], bf1h[1][3], (b_addr[1] + bbuf) ^ 32);

        // LDG A(kt+1) half 1
        if (kt < 7) {
#pragma unroll
            for (int j = 0; j < 4; j++)
                raw[j] = *(const float4*)(abase + (kt + 1) * 32 + 16 + j * 4);
        }

        // MMA g1 nt0-3
#pragma unroll
        for (int nt = 0; nt < 4; nt++) {
            uint32_t q0 = bf1h[nt >> 1][(nt & 1) * 2];
            uint32_t q1 = bf1h[nt >> 1][(nt & 1) * 2 + 1];
            MMA16(acc[0][nt], af1[0], q0, q1);
            MMA16(acc[1][nt], af1[1], q0, q1);
        }

        // B g1 second half
        uint32_t bf1l[2][4];
        LDM4(bf1l[0][0], bf1l[0][1], bf1l[0][2], bf1l[0][3], (b_addr[2] + bbuf) ^ 32);
        LDM4(bf1l[1][0], bf1l[1][1], bf1l[1][2], bf1l[1][3], (b_addr[3] + bbuf) ^ 32);

        // cvt + STS half 1
        if (kt < 7) {
            uint32_t v[8];
#pragma unroll
            for (int j = 0; j < 4; j++) {
                __half2 lo = __floats2half2_rn(raw[j].x, raw[j].y);
                __half2 hi = __floats2half2_rn(raw[j].z, raw[j].w);
                v[2 * j]     = *(uint32_t*)&lo;
                v[2 * j + 1] = *(uint32_t*)&hi;
            }
            STS128(a_st[2] + nab, v[0], v[1], v[2], v[3]);
            STS128(a_st[3] + nab, v[4], v[5], v[6], v[7]);
        }

        // MMA g1 nt4-7
#pragma unroll
        for (int nt = 4; nt < 8; nt++) {
            uint32_t q0 = bf1l[(nt - 4) >> 1][(nt & 1) * 2];
            uint32_t q1 = bf1l[(nt - 4) >> 1][(nt & 1) * 2 + 1];
            MMA16(acc[0][nt], af1[0], q0, q1);
            MMA16(acc[1][nt], af1[1], q0, q1);
        }

        // publish A(kt+1) frags: warp-local ordering only
        if (kt < 7) {
            __syncwarp();
            LDM4(af0[0][0], af0[0][1], af0[0][2], af0[0][3], (a_lm + nab));
            LDM4(af0[1][0], af0[1][1], af0[1][2], af0[1][3], (a_lm + nab) ^ 64);
            LDM4(af1[0][0], af1[0][1], af1[0][2], af1[0][3], (a_lm + nab) ^ 32);
            LDM4(af1[1][0], af1[1][1], af1[1][2], af1[1][3], (a_lm + nab) ^ 32 ^ 64);
        }
        (void)abuf;
    }

    // ---- epilogue: streaming stores ----
#pragma unroll
    for (int mt = 0; mt < 2; mt++) {
        const int r0 = wm + mt * 16 + g;
#pragma unroll
        for (int nt = 0; nt < 8; nt++) {
            const int c = wn + nt * 8 + 2 * t;
            __stcs((float2*)&Cb[(size_t)r0 * 256 + c],
                   make_float2(acc[mt][nt][0], acc[mt][nt][1]));
            __stcs((float2*)&Cb[(size_t)(r0 + 8) * 256 + c],
                   make_float2(acc[mt][nt][2], acc[mt][nt][3]));
        }
    }
}

// ---------------------------------------------------------------------------
extern "C" void kernel_launch(void* const* d_in, const int* in_sizes, int n_in,
                              void* d_out, int out_size)
{
    (void)in_sizes; (void)n_in; (void)out_size;
    const float* queries = (const float*)d_in[0];
    const float* feats   = (const float*)d_in[1];
    const float* W1 = (const float*)d_in[4];
    const float* b1 = (const float*)d_in[5];
    const float* W2 = (const float*)d_in[6];
    const float* b2 = (const float*)d_in[7];
    const float* W3 = (const float*)d_in[8];
    const float* b3 = (const float*)d_in[9];
    const float* W4 = (const float*)d_in[10];
    const float* b4 = (const float*)d_in[11];
    float* out = (float*)d_out;

    __half *wh = nullptr, *qh = nullptr;
    cudaGetSymbolAddress((void**)&wh, g_wh);
    cudaGetSymbolAddress((void**)&qh, g_qh);

    cudaFuncSetAttribute(mlp_fused,   cudaFuncAttributeMaxDynamicSharedMemorySize, MLP_SMEM);
    cudaFuncSetAttribute(gemm_logits, cudaFuncAttributeMaxDynamicSharedMemorySize, LOG_SMEM);

    prep_w<<<256, 256>>>(W1, W2, W3, W4);
    mlp_fused<<<16, 256, MLP_SMEM>>>(queries, wh, b1, b2, b3, b4, qh);
    gemm_logits<<<dim3(2, NF_ / 128, B_), 256, LOG_SMEM>>>(feats, qh, out);
}

// round 15
// speedup vs baseline: 2.0856x; 2.0856x over previous
#include <cuda_runtime.h>
#include <cuda_fp16.h>
#include <cstdint>
#include <cstddef>

#define KDIM 256
#define NQ_  1024
#define B_   4
#define NF_  65536

// scratch (__device__ globals: the sanctioned no-alloc path)
__device__ __half g_wh[4 * KDIM * KDIM];   // fp16 weights, [layer][out][in]
__device__ __half g_qh[NQ_ * KDIM];        // fp16 MLP output (logits B operand)

__device__ __forceinline__ uint32_t cvta_s(const void* p) {
    return (uint32_t)__cvta_generic_to_shared(p);
}

#define LDM4(r0, r1, r2, r3, addr) \
    asm volatile("ldmatrix.sync.aligned.m8n8.x4.shared.b16 {%0,%1,%2,%3}, [%4];" \
                 : "=r"(r0), "=r"(r1), "=r"(r2), "=r"(r3) : "r"(addr))

#define MMA16(c, a, b0, b1) \
    asm volatile("mma.sync.aligned.m16n8k16.row.col.f32.f16.f16.f32 " \
                 "{%0,%1,%2,%3},{%4,%5,%6,%7},{%8,%9},{%0,%1,%2,%3};" \
                 : "+f"((c)[0]), "+f"((c)[1]), "+f"((c)[2]), "+f"((c)[3]) \
                 : "r"((a)[0]), "r"((a)[1]), "r"((a)[2]), "r"((a)[3]), "r"(b0), "r"(b1))

#define CP16(dst, src) \
    asm volatile("cp.async.cg.shared.global [%0], [%1], 16;" :: "r"(dst), "l"(src))

// ---------------------------------------------------------------------------
// prep: convert the 4 weight matrices f32 -> fp16 (once per launch)
// ---------------------------------------------------------------------------
__global__ void prep_w(const float* __restrict__ W1, const float* __restrict__ W2,
                       const float* __restrict__ W3, const float* __restrict__ W4)
{
    int idx = blockIdx.x * 256 + threadIdx.x;          // 65536 float4 total
    const float* src = (idx < 16384) ? W1 : (idx < 32768) ? W2 : (idx < 49152) ? W3 : W4;
    int off = idx & 16383;
    float4 v = ((const float4*)src)[off];
    __half2 h0 = __floats2half2_rn(v.x, v.y);
    __half2 h1 = __floats2half2_rn(v.z, v.w);
    uint2 u;
    u.x = *(uint32_t*)&h0;
    u.y = *(uint32_t*)&h1;
    ((uint2*)g_wh)[idx] = u;
}

// ---------------------------------------------------------------------------
// Fused 4-layer MLP (unchanged from the 190.6us config; ~15us)
// ---------------------------------------------------------------------------
#define MLP_SMEM (65536 + 49152 + 4096)

__global__ __launch_bounds__(256) void mlp_fused(
    const float* __restrict__ Q, const __half* __restrict__ wh,
    const float* __restrict__ b1, const float* __restrict__ b2,
    const float* __restrict__ b3, const float* __restrict__ b4,
    __half* __restrict__ qh)
{
    extern __shared__ char sm[];
    char*  xb = sm;                        // 2 x 32768
    char*  ws = sm + 65536;                // 3 x 16384
    float* sb = (float*)(sm + 65536 + 49152);

    const int tid = threadIdx.x;
    const int w = tid >> 5, l = tid & 31;
    const int g = l >> 2, t = l & 3;
    const int wm = (w & 1) * 32;
    const int wn = (w >> 1) * 64;
    const int m0 = blockIdx.x * 64;

    sb[tid] = b1[tid]; sb[256 + tid] = b2[tid];
    sb[512 + tid] = b3[tid]; sb[768 + tid] = b4[tid];

#pragma unroll
    for (int i = 0; i < 16; i++) {
        int idx = tid + i * 256;
        int r = idx >> 6, k = (idx & 63) * 4;
        float4 v = *(const float4*)&Q[(size_t)(m0 + r) * KDIM + k];
        __half2 h0 = __floats2half2_rn(v.x, v.y);
        __half2 h1 = __floats2half2_rn(v.z, v.w);
        int chunk = k >> 5, c16 = (k & 31) >> 3, hi = (k >> 2) & 1;
        uint32_t ad = cvta_s(xb + chunk * 4096 + (r & 31) * 128
                             + ((((r >> 5) * 4) + c16) ^ (r & 7)) * 16 + hi * 8);
        asm volatile("st.shared.v2.b32 [%0], {%1,%2};"
                     :: "r"(ad), "r"(*(uint32_t*)&h0), "r"(*(uint32_t*)&h1));
    }

    uint32_t b_addr[4];
    {
        int n = wn + (l & 7) + ((l >> 4) & 1) * 8;
        int ck = (l >> 3) & 1;
#pragma unroll
        for (int p = 0; p < 4; p++) {
            int nn = n + p * 16;
            int cp = (((nn >> 7) * 4 + ck) ^ (nn & 7));
            b_addr[p] = cvta_s(ws + (nn & 127) * 128 + cp * 16);
        }
    }
    uint32_t wst[4];
#pragma unroll
    for (int c = 0; c < 4; c++) {
        int n = tid;
        wst[c] = cvta_s(ws + (n & 127) * 128 + ((((n >> 7) * 4) + c) ^ (n & 7)) * 16);
    }

    __syncthreads();

    for (int L = 0; L < 4; L++) {
        const __half* Wl = wh + (size_t)L * 65536;
        const uint32_t xbase = (uint32_t)(L & 1) * 32768;

        uint32_t a_addr[2];
        {
            int r = wm + (l & 7) + ((l >> 3) & 1) * 8;
            int ck = (l >> 4) & 1;
#pragma unroll
            for (int mt = 0; mt < 2; mt++) {
                int rr = r + mt * 16;
                int cp = (((rr >> 5) * 4 + ck) ^ (rr & 7));
                a_addr[mt] = cvta_s(xb + xbase + (rr & 31) * 128 + cp * 16);
            }
        }

#pragma unroll
        for (int s = 0; s < 2; s++) {
#pragma unroll
            for (int c = 0; c < 4; c++)
                CP16(wst[c] + s * 16384, Wl + (size_t)tid * KDIM + s * 32 + c * 8);
            asm volatile("cp.async.commit_group;");
        }

        float acc[2][8][4];
#pragma unroll
        for (int mt = 0; mt < 2; mt++)
#pragma unroll
            for (int nt = 0; nt < 8; nt++)
#pragma unroll
                for (int i = 0; i < 4; i++) acc[mt][nt][i] = 0.f;

#pragma unroll
        for (int kt = 0; kt < 8; kt++) {
            asm volatile("cp.async.wait_group 1;");
            __syncthreads();
            if (kt < 6) {
                int s = (kt + 2) % 3;
#pragma unroll
                for (int c = 0; c < 4; c++)
                    CP16(wst[c] + s * 16384, Wl + (size_t)tid * KDIM + (kt + 2) * 32 + c * 8);
            }
            asm volatile("cp.async.commit_group;");

            const uint32_t abuf = kt * 4096;
            const uint32_t bbuf = (kt % 3) * 16384;
#pragma unroll
            for (int g16 = 0; g16 < 2; g16++) {
                const uint32_t xo = g16 * 32;
                uint32_t a0[4], a1[4];
                LDM4(a0[0], a0[1], a0[2], a0[3], (a_addr[0] + abuf) ^ xo);
                LDM4(a1[0], a1[1], a1[2], a1[3], (a_addr[1] + abuf) ^ xo);
                uint32_t bf[4][4];
#pragma unroll
                for (int p = 0; p < 4; p++)
                    LDM4(bf[p][0], bf[p][1], bf[p][2], bf[p][3], (b_addr[p] + bbuf) ^ xo);
#pragma unroll
                for (int nt = 0; nt < 8; nt++) {
                    uint32_t q0 = bf[nt >> 1][(nt & 1) * 2];
                    uint32_t q1 = bf[nt >> 1][(nt & 1) * 2 + 1];
                    MMA16(acc[0][nt], a0, q0, q1);
                    MMA16(acc[1][nt], a1, q0, q1);
                }
            }
        }

        __syncthreads();

        if (L < 3) {
            const uint32_t pong = (uint32_t)((L & 1) ^ 1) * 32768;
#pragma unroll
            for (int mt = 0; mt < 2; mt++) {
#pragma unroll
                for (int nt = 0; nt < 8; nt++) {
                    int r = wm + mt * 16 + g;
                    int c = wn + nt * 8 + 2 * t;
                    float bi0 = sb[L * 256 + c], bi1 = sb[L * 256 + c + 1];
                    float v0 = fmaxf(acc[mt][nt][0] + bi0, 0.f);
                    float v1 = fmaxf(acc[mt][nt][1] + bi1, 0.f);
                    float v2 = fmaxf(acc[mt][nt][2] + bi0, 0.f);
                    float v3 = fmaxf(acc[mt][nt][3] + bi1, 0.f);
                    __half2 h01 = __floats2half2_rn(v0, v1);
                    __half2 h23 = __floats2half2_rn(v2, v3);
                    int chunk = c >> 5, c16 = (c & 31) >> 3, bo = (c & 7) * 2;
                    int r8 = r + 8;
                    uint32_t ad0 = cvta_s(xb + pong + chunk * 4096 + (r & 31) * 128
                                   + ((((r >> 5) * 4) + c16) ^ (r & 7)) * 16 + bo);
                    uint32_t ad1 = cvta_s(xb + pong + chunk * 4096 + (r8 & 31) * 128
                                   + ((((r8 >> 5) * 4) + c16) ^ (r8 & 7)) * 16 + bo);
                    asm volatile("st.shared.b32 [%0], %1;" :: "r"(ad0), "r"(*(uint32_t*)&h01));
                    asm volatile("st.shared.b32 [%0], %1;" :: "r"(ad1), "r"(*(uint32_t*)&h23));
                }
            }
        } else {
#pragma unroll
            for (int mt = 0; mt < 2; mt++) {
#pragma unroll
                for (int nt = 0; nt < 8; nt++) {
                    int r = m0 + wm + mt * 16 + g;
                    int c = wn + nt * 8 + 2 * t;
                    float bi0 = sb[768 + c], bi1 = sb[768 + c + 1];
                    __half2 h01 = __floats2half2_rn(acc[mt][nt][0] + bi0, acc[mt][nt][1] + bi1);
                    __half2 h23 = __floats2half2_rn(acc[mt][nt][2] + bi0, acc[mt][nt][3] + bi1);
                    *(__half2*)&qh[(size_t)r * KDIM + c]       = h01;
                    *(__half2*)&qh[(size_t)(r + 8) * KDIM + c] = h23;
                }
            }
        }
        __syncthreads();
    }
}

// ---------------------------------------------------------------------------
// Logits GEMM v9: R12/R13 schedule + 4-deep A ring + HALF the barriers.
//  - B: static 64KB tile (2 commit groups; group0 waited in prologue,
//    group1 waited at stage 3 top). No async ops in steady state.
//  - A: 4-slot ring (4x8KB, same layout as before). STS published TWO stages
//    ahead (A(kt+2) at stage kt), LDG three ahead -> every producer/consumer
//    and WAR pair spans >=2 stages -> __syncthreads only on ODD kt (4/tile).
//  - Coalesced CTA-cooperative A loads (R14's per-warp LDG was nL=32 poison).
// ---------------------------------------------------------------------------
#define LOG_SMEM (4 * 8192 + 8 * 8192)   // 98304: A ring 32K + B 64K
#define BOFF 32768

__global__ __launch_bounds__(256, 2)
void gemm_logits(const float* __restrict__ A, const __half* __restrict__ Bh,
                 float* __restrict__ C)
{
    extern __shared__ char sm[];
    char* As_ = sm;            // 4 x 8192 ring

    const int tid = threadIdx.x;
    const int w = tid >> 5, l = tid & 31;
    const int g = l >> 2, t = l & 3;
    const int wm = (w & 3) * 32;
    const int wn = (w >> 2) * 64;

    const int nb = blockIdx.x;   // n-inner: nb pair shares the A tile via L2
    const int mb = blockIdx.y;
    const long long bb = blockIdx.z;

    const float* Ab = A + bb * ((long long)NF_ * KDIM) + (size_t)mb * 128 * KDIM;
    const __half* Bb = Bh + bb * ((long long)256 * KDIM) + (size_t)nb * 128 * KDIM;
    float* Cb = C + bb * ((long long)NF_ * 256) + (size_t)mb * 128 * 256 + (size_t)nb * 128;

    // ---- B: whole 64KB tile via cp.async, 2 commit groups ----
    {
        int n = tid >> 1, c0 = (tid & 1) * 2;
        uint32_t d0 = cvta_s(sm + BOFF + (n & 63) * 128 + ((((n >> 6) * 4) + c0) ^ (n & 7)) * 16);
        uint32_t d1 = cvta_s(sm + BOFF + (n & 63) * 128 + ((((n >> 6) * 4) + c0 + 1) ^ (n & 7)) * 16);
        const __half* src = Bb + (size_t)n * KDIM + c0 * 8;
#pragma unroll
        for (int s = 0; s < 4; s++) { CP16(d0 + s * 8192, src + s * 32); CP16(d1 + s * 8192, src + s * 32 + 8); }
        asm volatile("cp.async.commit_group;");
#pragma unroll
        for (int s = 4; s < 8; s++) { CP16(d0 + s * 8192, src + s * 32); CP16(d1 + s * 8192, src + s * 32 + 8); }
        asm volatile("cp.async.commit_group;");
    }

    // ldmatrix A addrs (ring-slot-relative)
    uint32_t a_addr[2];
    {
        int r = wm + (l & 7) + ((l >> 3) & 1) * 8;
        int ck = (l >> 4) & 1;
#pragma unroll
        for (int mt = 0; mt < 2; mt++) {
            int rr = r + mt * 16;
            int cp = (((rr >> 6) * 4 + ck) ^ (rr & 7));
            a_addr[mt] = cvta_s(As_ + (rr & 63) * 128 + cp * 16);
        }
    }
    // ldmatrix B addrs (chunk-relative at BOFF)
    uint32_t b_addr[4];
    {
        int n = wn + (l & 7) + ((l >> 4) & 1) * 8;
        int ck = (l >> 3) & 1;
#pragma unroll
        for (int p = 0; p < 4; p++) {
            int nn = n + p * 16;
            int cp = (((nn >> 6) * 4 + ck) ^ (nn & 7));
            b_addr[p] = cvta_s(sm + BOFF + (nn & 63) * 128 + cp * 16);
        }
    }
    // A STS addrs (slot-relative) + single gmem base (coalesced: 4 lines/instr)
    const int fA = tid & 7;
    uint32_t sts_addr[4];
#pragma unroll
    for (int i = 0; i < 4; i++) {
        int r = i * 32 + (tid >> 3);
        int cp = (((r >> 6) * 4 + (fA >> 1)) ^ (r & 7));
        sts_addr[i] = cvta_s(As_ + (r & 63) * 128 + cp * 16 + (fA & 1) * 8);
    }
    const float* abase = Ab + (size_t)(tid >> 3) * KDIM + fA * 4;

    // ---- A prologue: A0,A1 -> smem slots 0,1; A2 -> pre[0] ----
    float4 pre[2][4];
#pragma unroll
    for (int i = 0; i < 4; i++) pre[0][i] = *(const float4*)(abase + (size_t)i * 32 * KDIM);        // A0
#pragma unroll
    for (int i = 0; i < 4; i++) pre[1][i] = *(const float4*)(abase + (size_t)i * 32 * KDIM + 32);   // A1
#pragma unroll
    for (int i = 0; i < 4; i++) {   // STS A0 -> slot 0
        __half2 h0 = __floats2half2_rn(pre[0][i].x, pre[0][i].y);
        __half2 h1 = __floats2half2_rn(pre[0][i].z, pre[0][i].w);
        asm volatile("st.shared.v2.b32 [%0], {%1,%2};"
                     :: "r"(sts_addr[i]), "r"(*(uint32_t*)&h0), "r"(*(uint32_t*)&h1));
    }
#pragma unroll
    for (int i = 0; i < 4; i++) pre[0][i] = *(const float4*)(abase + (size_t)i * 32 * KDIM + 64);   // A2
#pragma unroll
    for (int i = 0; i < 4; i++) {   // STS A1 -> slot 1
        __half2 h0 = __floats2half2_rn(pre[1][i].x, pre[1][i].y);
        __half2 h1 = __floats2half2_rn(pre[1][i].z, pre[1][i].w);
        asm volatile("st.shared.v2.b32 [%0], {%1,%2};"
                     :: "r"(sts_addr[i] + 8192), "r"(*(uint32_t*)&h0), "r"(*(uint32_t*)&h1));
    }

    float acc[2][8][4];
#pragma unroll
    for (int mt = 0; mt < 2; mt++)
#pragma unroll
        for (int nt = 0; nt < 8; nt++)
#pragma unroll
            for (int i = 0; i < 4; i++) acc[mt][nt][i] = 0.f;

    asm volatile("cp.async.wait_group 1;");   // B chunks 0-3 resident
    __syncthreads();                          // publishes A0,A1 + B visibility

    // prefetch g0(0)
    uint32_t a0[2][4], b0h[2][4];
    LDM4(a0[0][0], a0[0][1], a0[0][2], a0[0][3], a_addr[0]);
    LDM4(a0[1][0], a0[1][1], a0[1][2], a0[1][3], a_addr[1]);
    LDM4(b0h[0][0], b0h[0][1], b0h[0][2], b0h[0][3], b_addr[0]);
    LDM4(b0h[1][0], b0h[1][1], b0h[1][2], b0h[1][3], b_addr[1]);

#pragma unroll
    for (int kt = 0; kt < 8; kt++) {
        const uint32_t abuf = (uint32_t)(kt & 3) * 8192;
        const uint32_t bbuf = (uint32_t)kt * 8192;

        if (kt == 3)
            asm volatile("cp.async.wait_group 0;");   // B chunks 4-7 resident
                                                      // (first read: chunk 4 prefetch at stage-3 tail,
                                                      //  after the stage-3 mid barrier)

        // g0 second B half
        uint32_t b0l[2][4];
        LDM4(b0l[0][0], b0l[0][1], b0l[0][2], b0l[0][3], b_addr[2] + bbuf);
        LDM4(b0l[1][0], b0l[1][1], b0l[1][2], b0l[1][3], b_addr[3] + bbuf);

        // MMA g0 nt 0..3 (prefetched frags)
#pragma unroll
        for (int nt = 0; nt < 4; nt++) {
            uint32_t q0 = b0h[nt >> 1][(nt & 1) * 2];
            uint32_t q1 = b0h[nt >> 1][(nt & 1) * 2 + 1];
            MMA16(acc[0][nt], a0[0], q0, q1);
            MMA16(acc[1][nt], a0[1], q0, q1);
        }

        // g1 frags (first batch)
        uint32_t a1[2][4], b1h[2][4];
        LDM4(a1[0][0], a1[0][1], a1[0][2], a1[0][3], (a_addr[0] + abuf) ^ 32);
        LDM4(a1[1][0], a1[1][1], a1[1][2], a1[1][3], (a_addr[1] + abuf) ^ 32);
        LDM4(b1h[0][0], b1h[0][1], b1h[0][2], b1h[0][3], (b_addr[0] + bbuf) ^ 32);
        LDM4(b1h[1][0], b1h[1][1], b1h[1][2], b1h[1][3], (b_addr[1] + bbuf) ^ 32);

        // MMA g0 nt 4..7
#pragma unroll
        for (int nt = 4; nt < 8; nt++) {
            uint32_t q0 = b0l[(nt - 4) >> 1][(nt & 1) * 2];
            uint32_t q1 = b0l[(nt - 4) >> 1][(nt & 1) * 2 + 1];
            MMA16(acc[0][nt], a0[0], q0, q1);
            MMA16(acc[1][nt], a0[1], q0, q1);
        }

        // g1 second B half
        uint32_t b1l[2][4];
        LDM4(b1l[0][0], b1l[0][1], b1l[0][2], b1l[0][3], (b_addr[2] + bbuf) ^ 32);
        LDM4(b1l[1][0], b1l[1][1], b1l[1][2], b1l[1][3], (b_addr[3] + bbuf) ^ 32);

        // publish: STS A(kt+2) from pre[kt&1]; LDG A(kt+3) -> pre[(kt+1)&1]
        if (kt < 6) {
            const uint32_t nab = (uint32_t)((kt + 2) & 3) * 8192;
#pragma unroll
            for (int i = 0; i < 4; i++) {
                __half2 h0 = __floats2half2_rn(pre[kt & 1][i].x, pre[kt & 1][i].y);
                __half2 h1 = __floats2half2_rn(pre[kt & 1][i].z, pre[kt & 1][i].w);
                asm volatile("st.shared.v2.b32 [%0], {%1,%2};"
                             :: "r"(sts_addr[i] + nab),
                                "r"(*(uint32_t*)&h0), "r"(*(uint32_t*)&h1));
            }
        }
        if (kt < 5) {
#pragma unroll
            for (int i = 0; i < 4; i++)
                pre[(kt + 1) & 1][i] = *(const float4*)(abase + (size_t)i * 32 * KDIM + (kt + 3) * 32);
        }

        if (kt & 1) __syncthreads();   // barrier only on odd stages (4/tile)

        // MMA g1 nt 0..3
#pragma unroll
        for (int nt = 0; nt < 4; nt++) {
            uint32_t q0 = b1h[nt >> 1][(nt & 1) * 2];
            uint32_t q1 = b1h[nt >> 1][(nt & 1) * 2 + 1];
            MMA16(acc[0][nt], a1[0], q0, q1);
            MMA16(acc[1][nt], a1[1], q0, q1);
        }

        // prefetch g0(kt+1) — hidden behind remaining g1 MMAs
        if (kt < 7) {
            const uint32_t nab = (uint32_t)((kt + 1) & 3) * 8192;
            const uint32_t nbb = ((uint32_t)kt + 1) * 8192;
            LDM4(a0[0][0], a0[0][1], a0[0][2], a0[0][3], a_addr[0] + nab);
            LDM4(a0[1][0], a0[1][1], a0[1][2], a0[1][3], a_addr[1] + nab);
            LDM4(b0h[0][0], b0h[0][1], b0h[0][2], b0h[0][3], b_addr[0] + nbb);
            LDM4(b0h[1][0], b0h[1][1], b0h[1][2], b0h[1][3], b_addr[1] + nbb);
        }

        // MMA g1 nt 4..7
#pragma unroll
        for (int nt = 4; nt < 8; nt++) {
            uint32_t q0 = b1l[(nt - 4) >> 1][(nt & 1) * 2];
            uint32_t q1 = b1l[(nt - 4) >> 1][(nt & 1) * 2 + 1];
            MMA16(acc[0][nt], a1[0], q0, q1);
            MMA16(acc[1][nt], a1[1], q0, q1);
        }
    }

    // ---- epilogue: streaming stores ----
#pragma unroll
    for (int mt = 0; mt < 2; mt++) {
        const int r0 = wm + mt * 16 + g;
#pragma unroll
        for (int nt = 0; nt < 8; nt++) {
            const int c = wn + nt * 8 + 2 * t;
            __stcs((float2*)&Cb[(size_t)r0 * 256 + c],
                   make_float2(acc[mt][nt][0], acc[mt][nt][1]));
            __stcs((float2*)&Cb[(size_t)(r0 + 8) * 256 + c],
                   make_float2(acc[mt][nt][2], acc[mt][nt][3]));
        }
    }
}

// ---------------------------------------------------------------------------
extern "C" void kernel_launch(void* const* d_in, const int* in_sizes, int n_in,
                              void* d_out, int out_size)
{
    (void)in_sizes; (void)n_in; (void)out_size;
    const float* queries = (const float*)d_in[0];
    const float* feats   = (const float*)d_in[1];
    const float* W1 = (const float*)d_in[4];
    const float* b1 = (const float*)d_in[5];
    const float* W2 = (const float*)d_in[6];
    const float* b2 = (const float*)d_in[7];
    const float* W3 = (const float*)d_in[8];
    const float* b3 = (const float*)d_in[9];
    const float* W4 = (const float*)d_in[10];
    const float* b4 = (const float*)d_in[11];
    float* out = (float*)d_out;

    __half *wh = nullptr, *qh = nullptr;
    cudaGetSymbolAddress((void**)&wh, g_wh);
    cudaGetSymbolAddress((void**)&qh, g_qh);

    cudaFuncSetAttribute(mlp_fused,   cudaFuncAttributeMaxDynamicSharedMemorySize, MLP_SMEM);
    cudaFuncSetAttribute(gemm_logits, cudaFuncAttributeMaxDynamicSharedMemorySize, LOG_SMEM);

    prep_w<<<256, 256>>>(W1, W2, W3, W4);
    mlp_fused<<<16, 256, MLP_SMEM>>>(queries, wh, b1, b2, b3, b4, qh);
    gemm_logits<<<dim3(2, NF_ / 128, B_), 256, LOG_SMEM>>>(feats, qh, out);
}